// round 12
// baseline (speedup 1.0000x reference)
#include <cuda_runtime.h>
#include <cstdint>

#define NBLOCKS 740     // 5 CTAs/SM x 148 SMs -> exactly one wave
#define NTHREADS 256

// Per-block partials (overwritten every call — no zeroing needed).
__device__ float        g_part_iou[NBLOCKS];
__device__ float        g_part_mse[NBLOCKS];
__device__ unsigned int g_part_ninc[NBLOCKS];
// Completion counter; the last block resets it to 0 -> replay-safe.
__device__ unsigned int g_done_count = 0;

// 256-bit streaming load: two consecutive float4 boxes in one LDG.E.256.
__device__ __forceinline__ void ld256cs(const float4* p, float4& a, float4& b) {
    asm volatile("ld.global.cs.v8.f32 {%0,%1,%2,%3,%4,%5,%6,%7}, [%8];"
                 : "=f"(a.x), "=f"(a.y), "=f"(a.z), "=f"(a.w),
                   "=f"(b.x), "=f"(b.y), "=f"(b.z), "=f"(b.w)
                 : "l"(p));
}

__device__ __forceinline__ void process_box(const float4 p, const float4 g,
                                            float& iou_acc, float& mse_acc,
                                            unsigned int& ninc)
{
    // gt corners (cx, cy, w, h -> xyxy)
    float xminT = g.x - g.z * 0.5f;
    float xmaxT = g.x + g.z * 0.5f;
    float yminT = g.y - g.w * 0.5f;
    float ymaxT = g.y + g.w * 0.5f;
    // pred corners clipped to [0,1]
    float xminP = fmaxf(p.x - p.z * 0.5f, 0.0f);
    float xmaxP = fminf(p.x + p.z * 0.5f, 1.0f);
    float yminP = fmaxf(p.y - p.w * 0.5f, 0.0f);
    float ymaxP = fminf(p.y + p.w * 0.5f, 1.0f);
    // overlap box
    float o0 = fmaxf(xminT, xminP);
    float o1 = fmaxf(yminT, yminP);
    float o2 = fminf(xmaxT, xmaxP);
    float o3 = fminf(ymaxT, ymaxP);

    bool incorrect = (o2 < o0) || (o3 < o1);
    if (incorrect) {
        float dx = p.x - g.x;
        float dy = p.y - g.y;
        float dz = p.z - g.z;
        float dw = p.w - g.w;
        mse_acc += dx * dx + dy * dy + dz * dz + dw * dw;
        ninc++;
    } else {
        float area_p = p.z * p.w;
        float area_g = g.z * g.w;
        float inter  = (o2 - o0) * (o3 - o1);
        iou_acc += inter / (area_p + area_g - inter + 1e-7f);
    }
}

__global__ __launch_bounds__(NTHREADS, 5) void iou_fused_kernel(
    const float4* __restrict__ pr, const float4* __restrict__ gt,
    float* __restrict__ out, int n)
{
    float iou_acc = 0.0f, mse_acc = 0.0f;
    unsigned int ninc = 0u;

    const int tid     = blockIdx.x * NTHREADS + threadIdx.x;
    const int pstride = NBLOCKS * NTHREADS;      // stride in PAIRS
    const int npairs  = n >> 1;

    int i = tid;
    // Unroll x2 over pairs: 4 x 256-bit loads in flight (= 8 boxes / trip).
    for (; i + pstride < npairs; i += 2 * pstride) {
        float4 p0, p1, g0, g1, p2, p3, g2, g3;
        ld256cs(&pr[2 * i], p0, p1);
        ld256cs(&gt[2 * i], g0, g1);
        ld256cs(&pr[2 * (i + pstride)], p2, p3);
        ld256cs(&gt[2 * (i + pstride)], g2, g3);
        process_box(p0, g0, iou_acc, mse_acc, ninc);
        process_box(p1, g1, iou_acc, mse_acc, ninc);
        process_box(p2, g2, iou_acc, mse_acc, ninc);
        process_box(p3, g3, iou_acc, mse_acc, ninc);
    }
    for (; i < npairs; i += pstride) {
        float4 p0, p1, g0, g1;
        ld256cs(&pr[2 * i], p0, p1);
        ld256cs(&gt[2 * i], g0, g1);
        process_box(p0, g0, iou_acc, mse_acc, ninc);
        process_box(p1, g1, iou_acc, mse_acc, ninc);
    }
    // Odd trailing box (n odd): handled by global thread 0.
    if ((n & 1) && tid == 0) {
        process_box(__ldg(&pr[n - 1]), __ldg(&gt[n - 1]), iou_acc, mse_acc, ninc);
    }

    // Intra-warp reduce
    #pragma unroll
    for (int off = 16; off > 0; off >>= 1) {
        iou_acc += __shfl_down_sync(0xFFFFFFFFu, iou_acc, off);
        mse_acc += __shfl_down_sync(0xFFFFFFFFu, mse_acc, off);
        ninc    += __shfl_down_sync(0xFFFFFFFFu, ninc, off);
    }

    // Inter-warp reduce via smem
    __shared__ float s_iou[NTHREADS / 32];
    __shared__ float s_mse[NTHREADS / 32];
    __shared__ unsigned int s_ninc[NTHREADS / 32];
    const int lane = threadIdx.x & 31;
    const int warp = threadIdx.x >> 5;
    if (lane == 0) {
        s_iou[warp]  = iou_acc;
        s_mse[warp]  = mse_acc;
        s_ninc[warp] = ninc;
    }
    __syncthreads();
    if (warp == 0) {
        const int nw = NTHREADS / 32;
        float iou = (lane < nw) ? s_iou[lane] : 0.0f;
        float mse = (lane < nw) ? s_mse[lane] : 0.0f;
        unsigned int ni = (lane < nw) ? s_ninc[lane] : 0u;
        #pragma unroll
        for (int off = 4; off > 0; off >>= 1) {
            iou += __shfl_down_sync(0xFFFFFFFFu, iou, off);
            mse += __shfl_down_sync(0xFFFFFFFFu, mse, off);
            ni  += __shfl_down_sync(0xFFFFFFFFu, ni, off);
        }
        if (lane == 0) {
            g_part_iou[blockIdx.x]  = iou;
            g_part_mse[blockIdx.x]  = mse;
            g_part_ninc[blockIdx.x] = ni;
            // ncorr total = n - total ninc (derived in finalize)
        }
    }

    // Last-block-done finalization
    __shared__ bool is_last;
    if (threadIdx.x == 0) {
        __threadfence();
        unsigned int prev = atomicAdd(&g_done_count, 1u);
        is_last = (prev == (unsigned int)(gridDim.x - 1));
    }
    __syncthreads();
    if (!is_last) return;

    float iou = 0.0f, mse = 0.0f;
    unsigned long long ni = 0ull;
    for (int j = threadIdx.x; j < NBLOCKS; j += NTHREADS) {
        iou += g_part_iou[j];
        mse += g_part_mse[j];
        ni  += g_part_ninc[j];
    }
    #pragma unroll
    for (int off = 16; off > 0; off >>= 1) {
        iou += __shfl_down_sync(0xFFFFFFFFu, iou, off);
        mse += __shfl_down_sync(0xFFFFFFFFu, mse, off);
        ni  += __shfl_down_sync(0xFFFFFFFFu, ni, off);
    }
    __shared__ float f_iou[NTHREADS / 32];
    __shared__ float f_mse[NTHREADS / 32];
    __shared__ unsigned long long f_ninc[NTHREADS / 32];
    if (lane == 0) {
        f_iou[warp] = iou; f_mse[warp] = mse; f_ninc[warp] = ni;
    }
    __syncthreads();
    if (threadIdx.x == 0) {
        const int nw = NTHREADS / 32;
        double diou = 0.0, dmse = 0.0;
        unsigned long long tninc = 0ull;
        for (int w = 0; w < nw; w++) {
            diou += (double)f_iou[w];
            dmse += (double)f_mse[w];
            tninc += f_ninc[w];
        }
        unsigned long long tncorr = (unsigned long long)n - tninc;
        double mse_denom  = (double)(tninc * 4ull > 0ull ? tninc * 4ull : 1ull);
        double corr_denom = (double)(tncorr > 0ull ? tncorr : 1ull);
        float mse_mean = (float)(dmse / mse_denom);
        float iou_mean = (float)(diou / corr_denom);
        float res_full = iou_mean + (tninc > 0ull ? -mse_mean : 0.0f);
        out[0] = (tncorr > 0ull) ? res_full : -mse_mean;
        g_done_count = 0u;  // reset for next graph replay
    }
}

extern "C" void kernel_launch(void* const* d_in, const int* in_sizes, int n_in,
                              void* d_out, int out_size) {
    const float4* pr = (const float4*)d_in[0];
    const float4* gt = (const float4*)d_in[1];
    float* out = (float*)d_out;
    int n = in_sizes[0] / 4;  // floats -> boxes

    iou_fused_kernel<<<NBLOCKS, NTHREADS>>>(pr, gt, out, n);
}

// round 14
// speedup vs baseline: 1.0042x; 1.0042x over previous
#include <cuda_runtime.h>
#include <cstdint>

#define NBLOCKS 740       // 5 CTAs/SM x 148 SMs -> exactly one wave
#define NTHREADS 256
#define TILE_BOXES 1024   // 512 pairs: 2 pairs/thread per tile
#define TILE_PAIRS (TILE_BOXES / 2)

// Per-block partials (overwritten every call — no zeroing needed).
__device__ float        g_part_iou[NBLOCKS];
__device__ float        g_part_mse[NBLOCKS];
__device__ unsigned int g_part_ninc[NBLOCKS];
__device__ unsigned int g_part_ncorr[NBLOCKS];
// Dynamic work ticket + completion counter; reset by finisher -> replay-safe.
__device__ unsigned int g_ticket = 0;
__device__ unsigned int g_done_count = 0;

// 256-bit streaming load: two consecutive float4 boxes in one LDG.E.256.
__device__ __forceinline__ void ld256cs(const float4* p, float4& a, float4& b) {
    asm volatile("ld.global.cs.v8.f32 {%0,%1,%2,%3,%4,%5,%6,%7}, [%8];"
                 : "=f"(a.x), "=f"(a.y), "=f"(a.z), "=f"(a.w),
                   "=f"(b.x), "=f"(b.y), "=f"(b.z), "=f"(b.w)
                 : "l"(p));
}

__device__ __forceinline__ void process_box(const float4 p, const float4 g,
                                            float& iou_acc, float& mse_acc,
                                            unsigned int& ninc, unsigned int& ncorr)
{
    // gt corners (cx, cy, w, h -> xyxy)
    float xminT = g.x - g.z * 0.5f;
    float xmaxT = g.x + g.z * 0.5f;
    float yminT = g.y - g.w * 0.5f;
    float ymaxT = g.y + g.w * 0.5f;
    // pred corners clipped to [0,1]
    float xminP = fmaxf(p.x - p.z * 0.5f, 0.0f);
    float xmaxP = fminf(p.x + p.z * 0.5f, 1.0f);
    float yminP = fmaxf(p.y - p.w * 0.5f, 0.0f);
    float ymaxP = fminf(p.y + p.w * 0.5f, 1.0f);
    // overlap box
    float o0 = fmaxf(xminT, xminP);
    float o1 = fmaxf(yminT, yminP);
    float o2 = fminf(xmaxT, xmaxP);
    float o3 = fminf(ymaxT, ymaxP);

    bool incorrect = (o2 < o0) || (o3 < o1);
    if (incorrect) {
        float dx = p.x - g.x;
        float dy = p.y - g.y;
        float dz = p.z - g.z;
        float dw = p.w - g.w;
        mse_acc += dx * dx + dy * dy + dz * dz + dw * dw;
        ninc++;
    } else {
        float area_p = p.z * p.w;
        float area_g = g.z * g.w;
        float inter  = (o2 - o0) * (o3 - o1);
        iou_acc += inter / (area_p + area_g - inter + 1e-7f);
        ncorr++;
    }
}

__global__ __launch_bounds__(NTHREADS, 5) void iou_fused_kernel(
    const float4* __restrict__ pr, const float4* __restrict__ gt,
    float* __restrict__ out, int n)
{
    float iou_acc = 0.0f, mse_acc = 0.0f;
    unsigned int ninc = 0u, ncorr = 0u;

    const int tid    = threadIdx.x;
    const int npairs = n >> 1;
    const int ntiles = (npairs + TILE_PAIRS - 1) / TILE_PAIRS;

    __shared__ unsigned int s_tile;

    // Dynamic tile loop: fast (near-die) CTAs steal extra tiles.
    for (;;) {
        if (tid == 0) s_tile = atomicAdd(&g_ticket, 1u);
        __syncthreads();
        unsigned int t = s_tile;
        __syncthreads();   // protect s_tile before next iteration's overwrite
        if (t >= (unsigned int)ntiles) break;

        const int base = (int)t * TILE_PAIRS;
        const int i0 = base + tid;
        const int i1 = i0 + NTHREADS;

        if (i1 < npairs) {
            float4 p0, p1, g0, g1, p2, p3, g2, g3;
            ld256cs(&pr[2 * i0], p0, p1);
            ld256cs(&gt[2 * i0], g0, g1);
            ld256cs(&pr[2 * i1], p2, p3);
            ld256cs(&gt[2 * i1], g2, g3);
            process_box(p0, g0, iou_acc, mse_acc, ninc, ncorr);
            process_box(p1, g1, iou_acc, mse_acc, ninc, ncorr);
            process_box(p2, g2, iou_acc, mse_acc, ninc, ncorr);
            process_box(p3, g3, iou_acc, mse_acc, ninc, ncorr);
        } else {
            if (i0 < npairs) {
                float4 p0, p1, g0, g1;
                ld256cs(&pr[2 * i0], p0, p1);
                ld256cs(&gt[2 * i0], g0, g1);
                process_box(p0, g0, iou_acc, mse_acc, ninc, ncorr);
                process_box(p1, g1, iou_acc, mse_acc, ninc, ncorr);
            }
        }
    }

    // Odd trailing box (n odd): block 0 / thread 0.
    if ((n & 1) && blockIdx.x == 0 && tid == 0) {
        process_box(__ldg(&pr[n - 1]), __ldg(&gt[n - 1]), iou_acc, mse_acc, ninc, ncorr);
    }

    // Intra-warp reduce
    #pragma unroll
    for (int off = 16; off > 0; off >>= 1) {
        iou_acc += __shfl_down_sync(0xFFFFFFFFu, iou_acc, off);
        mse_acc += __shfl_down_sync(0xFFFFFFFFu, mse_acc, off);
        ninc    += __shfl_down_sync(0xFFFFFFFFu, ninc, off);
        ncorr   += __shfl_down_sync(0xFFFFFFFFu, ncorr, off);
    }

    // Inter-warp reduce via smem
    __shared__ float s_iou[NTHREADS / 32];
    __shared__ float s_mse[NTHREADS / 32];
    __shared__ unsigned int s_ninc[NTHREADS / 32];
    __shared__ unsigned int s_ncorr[NTHREADS / 32];
    const int lane = threadIdx.x & 31;
    const int warp = threadIdx.x >> 5;
    if (lane == 0) {
        s_iou[warp]   = iou_acc;
        s_mse[warp]   = mse_acc;
        s_ninc[warp]  = ninc;
        s_ncorr[warp] = ncorr;
    }
    __syncthreads();
    if (warp == 0) {
        const int nw = NTHREADS / 32;
        float iou = (lane < nw) ? s_iou[lane] : 0.0f;
        float mse = (lane < nw) ? s_mse[lane] : 0.0f;
        unsigned int ni = (lane < nw) ? s_ninc[lane]  : 0u;
        unsigned int nc = (lane < nw) ? s_ncorr[lane] : 0u;
        #pragma unroll
        for (int off = 4; off > 0; off >>= 1) {
            iou += __shfl_down_sync(0xFFFFFFFFu, iou, off);
            mse += __shfl_down_sync(0xFFFFFFFFu, mse, off);
            ni  += __shfl_down_sync(0xFFFFFFFFu, ni, off);
            nc  += __shfl_down_sync(0xFFFFFFFFu, nc, off);
        }
        if (lane == 0) {
            g_part_iou[blockIdx.x]   = iou;
            g_part_mse[blockIdx.x]   = mse;
            g_part_ninc[blockIdx.x]  = ni;
            g_part_ncorr[blockIdx.x] = nc;
        }
    }

    // Last-block-done finalization
    __shared__ bool is_last;
    if (threadIdx.x == 0) {
        __threadfence();
        unsigned int prev = atomicAdd(&g_done_count, 1u);
        is_last = (prev == (unsigned int)(gridDim.x - 1));
    }
    __syncthreads();
    if (!is_last) return;

    float iou = 0.0f, mse = 0.0f;
    unsigned long long ni = 0ull, nc = 0ull;
    for (int j = threadIdx.x; j < NBLOCKS; j += NTHREADS) {
        iou += g_part_iou[j];
        mse += g_part_mse[j];
        ni  += g_part_ninc[j];
        nc  += g_part_ncorr[j];
    }
    #pragma unroll
    for (int off = 16; off > 0; off >>= 1) {
        iou += __shfl_down_sync(0xFFFFFFFFu, iou, off);
        mse += __shfl_down_sync(0xFFFFFFFFu, mse, off);
        ni  += __shfl_down_sync(0xFFFFFFFFu, ni, off);
        nc  += __shfl_down_sync(0xFFFFFFFFu, nc, off);
    }
    __shared__ float f_iou[NTHREADS / 32];
    __shared__ float f_mse[NTHREADS / 32];
    __shared__ unsigned long long f_ni[NTHREADS / 32];
    __shared__ unsigned long long f_nc[NTHREADS / 32];
    if (lane == 0) {
        f_iou[warp] = iou; f_mse[warp] = mse; f_ni[warp] = ni; f_nc[warp] = nc;
    }
    __syncthreads();
    if (threadIdx.x == 0) {
        const int nw = NTHREADS / 32;
        double diou = 0.0, dmse = 0.0;
        unsigned long long tninc = 0ull, tncorr = 0ull;
        for (int w = 0; w < nw; w++) {
            diou += (double)f_iou[w];
            dmse += (double)f_mse[w];
            tninc += f_ni[w];
            tncorr += f_nc[w];
        }
        double mse_denom  = (double)(tninc * 4ull > 0ull ? tninc * 4ull : 1ull);
        double corr_denom = (double)(tncorr > 0ull ? tncorr : 1ull);
        float mse_mean = (float)(dmse / mse_denom);
        float iou_mean = (float)(diou / corr_denom);
        float res_full = iou_mean + (tninc > 0ull ? -mse_mean : 0.0f);
        out[0] = (tncorr > 0ull) ? res_full : -mse_mean;
        g_done_count = 0u;  // reset for next graph replay
        g_ticket     = 0u;  // reset ticket for next graph replay
    }
}

extern "C" void kernel_launch(void* const* d_in, const int* in_sizes, int n_in,
                              void* d_out, int out_size) {
    const float4* pr = (const float4*)d_in[0];
    const float4* gt = (const float4*)d_in[1];
    float* out = (float*)d_out;
    int n = in_sizes[0] / 4;  // floats -> boxes

    iou_fused_kernel<<<NBLOCKS, NTHREADS>>>(pr, gt, out, n);
}